// round 6
// baseline (speedup 1.0000x reference)
#include <cuda_runtime.h>
#include <math.h>

// QuantumPoolingLayer R6: R2 layout (1024 self-contained blocks, 512 KiB each,
// full 128B-line coalescing) but 3 blocks/SM (48 warps) with batch-4 loads.
// Thesis: DRAM% tracks warps x MLP (queue pressure), not block granularity.

#define NQ 4

struct c32 { float x, y; };
__device__ __forceinline__ c32 cadd(c32 a, c32 b){ return {a.x+b.x, a.y+b.y}; }
__device__ __forceinline__ c32 cmul(c32 a, c32 b){
    return { fmaf(a.x, b.x, -a.y*b.y), fmaf(a.x, b.y, a.y*b.x) };
}

// x[4] = tanh-normalized pooled values, w -> 24 floats [layer][qubit][phi,th,om].
__device__ __forceinline__ float simulate_sample(const float x[4], const float* __restrict__ w)
{
    c32 s[16];
#pragma unroll
    for (int k = 0; k < 16; k++) s[k] = {0.f, 0.f};
    s[0].x = 1.f;

    // Initial RY(x*pi); wire q <-> bit (3-q) => mask = 8>>q.
#pragma unroll
    for (int q = 0; q < NQ; q++) {
        float half = x[q] * 1.57079632679489662f;
        float sn, cs; __sincosf(half, &sn, &cs);
        const int m = 8 >> q;
#pragma unroll
        for (int k = 0; k < 16; k++) {
            if (!(k & m)) {
                c32 v0 = s[k], v1 = s[k | m];
                s[k]     = { cs*v0.x - sn*v1.x, cs*v0.y - sn*v1.y };
                s[k | m] = { sn*v0.x + cs*v1.x, sn*v0.y + cs*v1.y };
            }
        }
    }

#pragma unroll
    for (int layer = 0; layer < 2; layer++) {
#pragma unroll
        for (int q = 0; q < NQ; q++) {
            const float* g = w + (layer * 4 + q) * 3;
            float phi = g[0], th = g[1], om = g[2];
            float stt, ctt; __sincosf(0.5f * th, &stt, &ctt);
            float sa, ca;  __sincosf(0.5f * (phi + om), &sa, &ca);
            float sb, cb;  __sincosf(0.5f * (phi - om), &sb, &cb);
            c32 U00 = { ctt * ca, -ctt * sa };
            c32 U01 = { -stt * cb, -stt * sb };
            c32 U10 = { stt * cb, -stt * sb };
            c32 U11 = { ctt * ca,  ctt * sa };
            const int m = 8 >> q;
#pragma unroll
            for (int k = 0; k < 16; k++) {
                if (!(k & m)) {
                    c32 v0 = s[k], v1 = s[k | m];
                    c32 n0 = cadd(cmul(U00, v0), cmul(U01, v1));
                    c32 n1 = cadd(cmul(U10, v0), cmul(U11, v1));
                    s[k] = n0; s[k | m] = n1;
                }
            }
        }
        // CNOT(c,t) for all c<t in order: amplitude swaps.
#pragma unroll
        for (int c = 0; c < NQ; c++) {
#pragma unroll
            for (int t = c + 1; t < NQ; t++) {
                const int cm = 8 >> c, tm = 8 >> t;
#pragma unroll
                for (int k = 0; k < 16; k++) {
                    if ((k & cm) && !(k & tm)) {
                        c32 tmp = s[k]; s[k] = s[k | tm]; s[k | tm] = tmp;
                    }
                }
            }
        }
    }

    float p = 0.f;
#pragma unroll
    for (int k = 0; k < 16; k++) {
        float pr = fmaf(s[k].x, s[k].x, s[k].y * s[k].y);
        p += (k < 8) ? pr : -pr;
    }
    return p;
}

// Block: 512 threads, 3 blocks/SM. blockIdx = (m_chunk in [0,16), b in [0,64)).
// Thread (lane = tid&7 -> 4 consecutive m, g = tid>>3 -> row) accumulates two
// j-half partials with batch-4 loads in flight; smem reduce by quadrant;
// warp 0 simulates the chunk's 32 samples.
__global__ void __launch_bounds__(512, 3)
qpl_kernel(const float* __restrict__ in, const float* __restrict__ w, float* __restrict__ out)
{
    const int mc = blockIdx.x;       // m chunk: 32 m-values
    const int b  = blockIdx.y;
    const int tid  = threadIdx.x;
    const int lane = tid & 7;        // float4 lane: m_local = lane*4 .. +3
    const int g    = tid >> 3;       // row 0..63

    const float* base = in
        + (((size_t)b * 64 + g) * 64) * 512   // (b, row, j=0, m=0)
        + mc * 32 + (lane << 2);

    float4 a0 = {0.f,0.f,0.f,0.f};   // j in [0,32)
    float4 a1 = {0.f,0.f,0.f,0.f};   // j in [32,64)

#pragma unroll
    for (int j0 = 0; j0 < 32; j0 += 4) {
        float4 v[4];
#pragma unroll
        for (int k = 0; k < 4; k++)
            v[k] = __ldcs(reinterpret_cast<const float4*>(base + (size_t)(j0 + k) * 512));
#pragma unroll
        for (int k = 0; k < 4; k++) {
            a0.x += v[k].x; a0.y += v[k].y; a0.z += v[k].z; a0.w += v[k].w;
        }
    }
#pragma unroll
    for (int j0 = 32; j0 < 64; j0 += 4) {
        float4 v[4];
#pragma unroll
        for (int k = 0; k < 4; k++)
            v[k] = __ldcs(reinterpret_cast<const float4*>(base + (size_t)(j0 + k) * 512));
#pragma unroll
        for (int k = 0; k < 4; k++) {
            a1.x += v[k].x; a1.y += v[k].y; a1.z += v[k].z; a1.w += v[k].w;
        }
    }

    const int ihi = g >> 5;          // row half
    __shared__ float4 part[4][32][8];            // [quad][row-subgroup][lane], 16 KB
    __shared__ float  quads[4][32];              // [quad][m_local]
    part[ihi * 2 + 0][g & 31][lane] = a0;
    part[ihi * 2 + 1][g & 31][lane] = a1;
    __syncthreads();

    if (tid < 32) {
        // Reduce 32 row-partials per (quad, lane)
        const int quad = tid >> 3, ln = tid & 7;
        float4 ssum = {0.f,0.f,0.f,0.f};
#pragma unroll
        for (int k = 0; k < 32; k++) {
            float4 v = part[quad][k][ln];
            ssum.x += v.x; ssum.y += v.y; ssum.z += v.z; ssum.w += v.w;
        }
        quads[quad][ln * 4 + 0] = ssum.x;
        quads[quad][ln * 4 + 1] = ssum.y;
        quads[quad][ln * 4 + 2] = ssum.z;
        quads[quad][ln * 4 + 3] = ssum.w;
        __syncwarp();

        // Each of the 32 threads simulates one sample
        const int mm = mc * 32 + tid;            // global m in [0,512)
        float x[4];
#pragma unroll
        for (int q = 0; q < 4; q++)
            x[q] = tanhf(quads[q][tid] * (1.0f / 1024.0f));

        // widx = (b*512 + mm) // 64 = b*8 + (mm >> 6) = b*8 + (mc >> 1)
        const float* wp = w + ((size_t)(b * 8 + (mc >> 1))) * 24;
        out[b * 512 + mm] = simulate_sample(x, wp);
    }
}

extern "C" void kernel_launch(void* const* d_in, const int* in_sizes, int n_in,
                              void* d_out, int out_size)
{
    const float* in = (const float*)d_in[0];
    const float* w  = (const float*)d_in[1];
    if (n_in >= 2 && in_sizes[0] < in_sizes[1]) {   // defensive: identify by size
        in = (const float*)d_in[1];
        w  = (const float*)d_in[0];
    }
    dim3 grid(16, 64);
    qpl_kernel<<<grid, 512>>>(in, w, (float*)d_out);
}

// round 7
// speedup vs baseline: 1.1243x; 1.1243x over previous
#include <cuda_runtime.h>
#include <math.h>

// QuantumPoolingLayer R7: DRAM-page-locality attack.
//  K1: block = (b, 4-row group) -> streams a CONTIGUOUS 256 KB span (all m),
//      accumulates per-(colhalf, m) partials, writes 4 MB scratch. 1024 blocks.
//  K2: combine 16 rowgroup partials -> 4 quadrants per sample, tanh + 4-qubit sim.

#define NQ 4

__device__ float g_part[64 * 16 * 2 * 512];   // [b][rg][ch][m] partial sums (4 MB)

struct c32 { float x, y; };
__device__ __forceinline__ c32 cadd(c32 a, c32 b){ return {a.x+b.x, a.y+b.y}; }
__device__ __forceinline__ c32 cmul(c32 a, c32 b){
    return { fmaf(a.x, b.x, -a.y*b.y), fmaf(a.x, b.y, a.y*b.x) };
}

__device__ __forceinline__ float simulate_sample(const float x[4], const float* __restrict__ w)
{
    c32 s[16];
#pragma unroll
    for (int k = 0; k < 16; k++) s[k] = {0.f, 0.f};
    s[0].x = 1.f;

    // Initial RY(x*pi); wire q <-> bit (3-q) => mask = 8>>q.
#pragma unroll
    for (int q = 0; q < NQ; q++) {
        float half = x[q] * 1.57079632679489662f;
        float sn, cs; __sincosf(half, &sn, &cs);
        const int m = 8 >> q;
#pragma unroll
        for (int k = 0; k < 16; k++) {
            if (!(k & m)) {
                c32 v0 = s[k], v1 = s[k | m];
                s[k]     = { cs*v0.x - sn*v1.x, cs*v0.y - sn*v1.y };
                s[k | m] = { sn*v0.x + cs*v1.x, sn*v0.y + cs*v1.y };
            }
        }
    }

#pragma unroll
    for (int layer = 0; layer < 2; layer++) {
#pragma unroll
        for (int q = 0; q < NQ; q++) {
            const float* g = w + (layer * 4 + q) * 3;
            float phi = g[0], th = g[1], om = g[2];
            float stt, ctt; __sincosf(0.5f * th, &stt, &ctt);
            float sa, ca;  __sincosf(0.5f * (phi + om), &sa, &ca);
            float sb, cb;  __sincosf(0.5f * (phi - om), &sb, &cb);
            c32 U00 = { ctt * ca, -ctt * sa };
            c32 U01 = { -stt * cb, -stt * sb };
            c32 U10 = { stt * cb, -stt * sb };
            c32 U11 = { ctt * ca,  ctt * sa };
            const int m = 8 >> q;
#pragma unroll
            for (int k = 0; k < 16; k++) {
                if (!(k & m)) {
                    c32 v0 = s[k], v1 = s[k | m];
                    c32 n0 = cadd(cmul(U00, v0), cmul(U01, v1));
                    c32 n1 = cadd(cmul(U10, v0), cmul(U11, v1));
                    s[k] = n0; s[k | m] = n1;
                }
            }
        }
        // CNOT(c,t) for all c<t in order: amplitude swaps.
#pragma unroll
        for (int c = 0; c < NQ; c++) {
#pragma unroll
            for (int t = c + 1; t < NQ; t++) {
                const int cm = 8 >> c, tm = 8 >> t;
#pragma unroll
                for (int k = 0; k < 16; k++) {
                    if ((k & cm) && !(k & tm)) {
                        c32 tmp = s[k]; s[k] = s[k | tm]; s[k | tm] = tmp;
                    }
                }
            }
        }
    }

    float p = 0.f;
#pragma unroll
    for (int k = 0; k < 16; k++) {
        float pr = fmaf(s[k].x, s[k].x, s[k].y * s[k].y);
        p += (k < 8) ? pr : -pr;
    }
    return p;
}

// K1: grid (rg=16, b=64), 512 threads, 2 blocks/SM.
// Thread: ml = tid&127 (float4 over m: m = ml*4..+3), p = tid>>7 (0..3).
// Block streams rows [rg*4, rg*4+4), all j, all m: 256 KB contiguous.
// Thread covers (i,j) pairs with j ≡ p (mod 4). For each row, its first 8
// iterations are j<32 (colhalf 0), next 8 are j>=32 (colhalf 1).
__global__ void __launch_bounds__(512, 2)
pool_kernel(const float* __restrict__ in)
{
    const int rg = blockIdx.x;           // 4-row group, 0..15
    const int b  = blockIdx.y;
    const int tid = threadIdx.x;
    const int ml  = tid & 127;           // m float4 lane
    const int p   = tid >> 7;            // 0..3

    const float* tb = in
        + ((size_t)(b * 64 + rg * 4) * 64) * 512   // start of the 4-row span
        + (size_t)p * 512 + (ml << 2);

    float4 acc0 = {0.f,0.f,0.f,0.f};     // colhalf 0 (j < 32)
    float4 acc1 = {0.f,0.f,0.f,0.f};     // colhalf 1 (j >= 32)

#pragma unroll
    for (int il = 0; il < 4; il++) {
        const float* rbase = tb + (size_t)il * 64 * 512;
        {
            float4 v[8];
#pragma unroll
            for (int k = 0; k < 8; k++)
                v[k] = __ldcs(reinterpret_cast<const float4*>(rbase + (size_t)k * 2048));
#pragma unroll
            for (int k = 0; k < 8; k++) {
                acc0.x += v[k].x; acc0.y += v[k].y; acc0.z += v[k].z; acc0.w += v[k].w;
            }
        }
        {
            float4 v[8];
#pragma unroll
            for (int k = 0; k < 8; k++)
                v[k] = __ldcs(reinterpret_cast<const float4*>(rbase + (size_t)(k + 8) * 2048));
#pragma unroll
            for (int k = 0; k < 8; k++) {
                acc1.x += v[k].x; acc1.y += v[k].y; acc1.z += v[k].z; acc1.w += v[k].w;
            }
        }
    }

    __shared__ float4 part[4][2][128];   // [p][ch][ml], 16 KB
    part[p][0][ml] = acc0;
    part[p][1][ml] = acc1;
    __syncthreads();

    if (tid < 256) {
        const int ch  = tid >> 7;
        const int mlr = tid & 127;
        float4 ssum = {0.f,0.f,0.f,0.f};
#pragma unroll
        for (int q = 0; q < 4; q++) {
            float4 v = part[q][ch][mlr];
            ssum.x += v.x; ssum.y += v.y; ssum.z += v.z; ssum.w += v.w;
        }
        float4* dst = reinterpret_cast<float4*>(g_part) +
                      (size_t)(((b * 16 + rg) * 2 + ch) * 128 + mlr);
        *dst = ssum;
    }
}

// K2: one thread per sample (32768). Combine 16 rowgroup partials per colhalf
// into 4 quadrants (rh = rg>>3), then tanh + sim.
__global__ void __launch_bounds__(128)
sim_kernel(const float* __restrict__ w, float* __restrict__ out)
{
    const int n = blockIdx.x * 128 + threadIdx.x;   // sample = b*512 + m
    const int b = n >> 9;
    const int m = n & 511;

    float quad[4] = {0.f, 0.f, 0.f, 0.f};
#pragma unroll
    for (int rg = 0; rg < 16; rg++) {
        const int rh = rg >> 3;
#pragma unroll
        for (int ch = 0; ch < 2; ch++) {
            quad[rh * 2 + ch] += g_part[(size_t)(((b * 16 + rg) * 2 + ch) * 512 + m)];
        }
    }

    float x[4];
#pragma unroll
    for (int q = 0; q < 4; q++)
        x[q] = tanhf(quad[q] * (1.0f / 1024.0f));

    const float* wp = w + (size_t)(n >> 6) * 24;   // widx = n // 64
    out[n] = simulate_sample(x, wp);
}

extern "C" void kernel_launch(void* const* d_in, const int* in_sizes, int n_in,
                              void* d_out, int out_size)
{
    const float* in = (const float*)d_in[0];
    const float* w  = (const float*)d_in[1];
    if (n_in >= 2 && in_sizes[0] < in_sizes[1]) {   // defensive: identify by size
        in = (const float*)d_in[1];
        w  = (const float*)d_in[0];
    }
    dim3 grid1(16, 64);
    pool_kernel<<<grid1, 512>>>(in);
    sim_kernel<<<256, 128>>>(w, (float*)d_out);
}